// round 12
// baseline (speedup 1.0000x reference)
#include <cuda_runtime.h>
#include <cuda_bf16.h>
#include <math.h>
#include <stdint.h>

// ConLoss (NT-Xent): z = normalize(concat(h1,h2)) [8192,512]; sim = z z^T; T=0.5
// loss_i = -2*sim[i,i^4096] + log(sum_{j!=i} exp(2*sim_ij)); out = mean.
// Round 12: persistent CTAs (2/SM) + dynamic tile stealing with 1-deep
// lookahead prefetch (B-ring never drains across tiles), hoisted cp.async
// addressing, local-index epilogue. Upper-triangle symmetry as R11.

#define NROWS 8192
#define HALF  4096
#define D     512

#define THREADS 256
#define NCTA 296                      // 2 per SM x 148 SMs
#define BT 128                        // tile dim
#define NT (NROWS / BT)               // 64
#define NTILES (NT * (NT + 1) / 2)    // 2080
#define NKC 4                         // k chunks of 128

#define CH_BYTES (BT * 128)           // 16 KB per operand chunk
#define STAGE_BYTES (2 * CH_BYTES)    // 32 KB (A+B)
#define SMEM_TOTAL (2 * STAGE_BYTES)  // 64 KB

// exp(2*sim) = 2^(acc * 2*log2e/256), acc = 256*sim (z scaled by 16)
#define EXP_SCALE 0.0112710550f
#define POS_SCALE 0.0078125f          // 2/256

__device__ __align__(16) uint8_t g_z8[NROWS * D];
__device__ float g_S[NROWS];
__device__ float g_pos[NROWS];
__device__ unsigned int g_cnt = 0;
__device__ unsigned int g_tile = 0;

// ---------------- helpers ----------------
__device__ __forceinline__ uint32_t smem_u32(const void* p) {
    uint32_t a;
    asm("{ .reg .u64 t; cvta.to.shared.u64 t, %1; cvt.u32.u64 %0, t; }" : "=r"(a) : "l"(p));
    return a;
}
__device__ __forceinline__ uint32_t SWZ(uint32_t off) {   // SW128 swizzle
    return off ^ ((off >> 3) & 0x70);
}
__device__ __forceinline__ void cp16(uint32_t dst, const void* src) {
    asm volatile("cp.async.cg.shared.global [%0], [%1], 16;" :: "r"(dst), "l"(src));
}
#define CP_COMMIT() asm volatile("cp.async.commit_group;" ::: "memory")
#define CP_WAIT(n)  asm volatile("cp.async.wait_group %0;" :: "n"(n) : "memory")

__device__ __forceinline__ void ldmx4(uint32_t* r, uint32_t addr) {
    asm volatile("ldmatrix.sync.aligned.m8n8.x4.shared.b16 {%0,%1,%2,%3}, [%4];"
                 : "=r"(r[0]), "=r"(r[1]), "=r"(r[2]), "=r"(r[3]) : "r"(addr));
}
__device__ __forceinline__ void mma_fp8(float* c, const uint32_t* a, const uint32_t* b) {
    asm volatile("mma.sync.aligned.m16n8k32.row.col.f32.e4m3.e4m3.f32 "
                 "{%0,%1,%2,%3}, {%4,%5,%6,%7}, {%8,%9}, {%0,%1,%2,%3};"
                 : "+f"(c[0]), "+f"(c[1]), "+f"(c[2]), "+f"(c[3])
                 : "r"(a[0]), "r"(a[1]), "r"(a[2]), "r"(a[3]), "r"(b[0]), "r"(b[1]));
}
__device__ __forceinline__ float ex2f(float x) {
    float y;
    asm("ex2.approx.f32 %0, %1;" : "=f"(y) : "f"(x));
    return y;
}
__device__ __forceinline__ uint32_t pack_e4m3(float f0, float f1, float f2, float f3) {
    uint16_t lo, hi;
    asm("cvt.rn.satfinite.e4m3x2.f32 %0, %1, %2;" : "=h"(lo) : "f"(f1), "f"(f0));
    asm("cvt.rn.satfinite.e4m3x2.f32 %0, %1, %2;" : "=h"(hi) : "f"(f3), "f"(f2));
    return (uint32_t)lo | ((uint32_t)hi << 16);
}

// decode flat upper-triangle index -> (rt, ct), ct >= rt
__device__ __forceinline__ void decode_tile(int flat, int& rt, int& ct) {
    int r = (int)((2 * NT + 1 - sqrtf((float)((2 * NT + 1) * (2 * NT + 1) - 8 * flat))) * 0.5f);
    while (r * (2 * NT + 1 - r) / 2 > flat) r--;
    while ((r + 1) * (2 * NT - r) / 2 <= flat) r++;
    rt = r;
    ct = r + (flat - r * (2 * NT + 1 - r) / 2);
}

// ---------------- kernels ----------------
// One warp per row: normalize, scale by 16, write e4m3. Zeroes g_S, seeds g_tile.
__global__ void norm_kernel(const float* __restrict__ a, const float* __restrict__ b) {
    int gt = blockIdx.x * blockDim.x + threadIdx.x;
    if (gt == 0) g_tile = NCTA;      // CTAs 0..NCTA-1 take tiles == their bid first
    if (gt < NROWS) g_S[gt] = 0.0f;
    int gw   = gt >> 5;
    int lane = threadIdx.x & 31;
    if (gw >= NROWS) return;
    const float* src = (gw < HALF) ? (a + (size_t)gw * D) : (b + (size_t)(gw - HALF) * D);
    const float4* s4 = (const float4*)src;
    float4 v[4];
    float ss = 0.0f;
#pragma unroll
    for (int l = 0; l < 4; l++) {
        v[l] = s4[lane + l * 32];
        ss += v[l].x * v[l].x + v[l].y * v[l].y + v[l].z * v[l].z + v[l].w * v[l].w;
    }
#pragma unroll
    for (int m = 16; m; m >>= 1) ss += __shfl_xor_sync(0xffffffffu, ss, m);
    float inv = 16.0f / fmaxf(sqrtf(ss), 1e-8f);
    uint32_t* d32 = (uint32_t*)(g_z8 + (size_t)gw * D);
#pragma unroll
    for (int l = 0; l < 4; l++) {
        float4 w = v[l];
        d32[lane + 32 * l] = pack_e4m3(w.x * inv, w.y * inv, w.z * inv, w.w * inv);
    }
}

__global__ __launch_bounds__(THREADS, 2) void gemm_kernel(float* __restrict__ out) {
    extern __shared__ __align__(1024) char smem[];
    const uint32_t sb = smem_u32(smem);
    const int tid  = threadIdx.x;
    const int wid  = tid >> 5;
    const int lane = tid & 31;
    const int wm = wid & 3;        // row warp: 32 rows
    const int wn = wid >> 2;       // col warp: 64 cols

    // ---- hoisted cp.async addressing (per thread) ----
    const int ld_row = tid >> 3;          // 0..31
    const int ld_g   = tid & 7;           // 0..7 (16B groups)
    uint32_t dsw[4];
#pragma unroll
    for (int l = 0; l < 4; l++)
        dsw[l] = SWZ((ld_row + 32 * l) * 128 + ld_g * 16);

    // ---- hoisted ldmatrix addressing ----
    const int a_row0 = wm * 32 + (lane & 15);
    const uint32_t a_off0 = SWZ(a_row0 * 128 + (lane >> 4) * 16);
    const uint32_t a_off1 = SWZ((a_row0 + 16) * 128 + (lane >> 4) * 16);
    const int b_row0 = wn * 64 + (lane & 7) + ((lane & 16) ? 8 : 0);
    uint32_t b_off[4];
#pragma unroll
    for (int q = 0; q < 4; q++)
        b_off[q] = SWZ((b_row0 + q * 16) * 128 + ((lane & 8) ? 16 : 0));

    // epilogue local indices
    const int lr0 = wm * 32 + (lane >> 2);      // + mf*16 + h*8
    const int lc0 = wn * 64 + (lane & 3) * 2;   // + nf*8 + e

    const uint4* Z4 = (const uint4*)g_z8;       // 32 uint4 per row

    __shared__ unsigned int s_nxt;

    int cur = blockIdx.x;                       // first tile = bid (g_tile seeded to NCTA)
    int rt, ct;
    decode_tile(cur, rt, ct);
    int row_base = rt * BT, col_base = ct * BT;

    // prologue: chunk 0 of first tile
    {
        const uint4* as = Z4 + (size_t)(row_base + ld_row) * 32 + ld_g;
        const uint4* bs = Z4 + (size_t)(col_base + ld_row) * 32 + ld_g;
#pragma unroll
        for (int l = 0; l < 4; l++) {
            cp16(sb + dsw[l], as + (size_t)l * 32 * 32);
            cp16(sb + CH_BYTES + dsw[l], bs + (size_t)l * 32 * 32);
        }
        CP_COMMIT();
    }

    int st = 0;   // stage of current chunk

    while (cur < NTILES) {
        if (tid == 0) s_nxt = atomicAdd(&g_tile, 1u);

        float c[2][8][4];
#pragma unroll
        for (int mf = 0; mf < 2; mf++)
#pragma unroll
            for (int nf = 0; nf < 8; nf++)
#pragma unroll
                for (int e = 0; e < 4; e++) c[mf][nf][e] = 0.0f;

        int nxt = 0, nrt = 0, nct = 0;
        const uint4* as = Z4 + (size_t)(row_base + ld_row) * 32 + ld_g;
        const uint4* bs = Z4 + (size_t)(col_base + ld_row) * 32 + ld_g;

#pragma unroll
        for (int kc = 0; kc < NKC; kc++) {
            CP_WAIT(0);             // this chunk resident
            __syncthreads();        // publish loads + all warps done w/ other stage
            if (kc == 0) {
                nxt = (int)s_nxt;
                if (nxt < NTILES) decode_tile(nxt, nrt, nct);
            }
            // prefetch next chunk into the other stage
            const uint32_t dst = sb + (st ^ 1) * STAGE_BYTES;
            if (kc < NKC - 1) {
                const uint4* a2 = as + (size_t)(kc + 1) * 8;
                const uint4* b2 = bs + (size_t)(kc + 1) * 8;
#pragma unroll
                for (int l = 0; l < 4; l++) {
                    cp16(dst + dsw[l], a2 + (size_t)l * 32 * 32);
                    cp16(dst + CH_BYTES + dsw[l], b2 + (size_t)l * 32 * 32);
                }
                CP_COMMIT();
            } else if (nxt < NTILES) {   // next tile's chunk 0
                const uint4* a2 = Z4 + (size_t)(nrt * BT + ld_row) * 32 + ld_g;
                const uint4* b2 = Z4 + (size_t)(nct * BT + ld_row) * 32 + ld_g;
#pragma unroll
                for (int l = 0; l < 4; l++) {
                    cp16(dst + dsw[l], a2 + (size_t)l * 32 * 32);
                    cp16(dst + CH_BYTES + dsw[l], b2 + (size_t)l * 32 * 32);
                }
                CP_COMMIT();
            }

            const uint32_t Ab = sb + st * STAGE_BYTES;
            const uint32_t Bb = Ab + CH_BYTES;
#pragma unroll
            for (int k32 = 0; k32 < 4; k32++) {
                const uint32_t cb = k32 * 32;
                uint32_t af[2][4];
                ldmx4(af[0], Ab + (a_off0 ^ cb));
                ldmx4(af[1], Ab + (a_off1 ^ cb));
#pragma unroll
                for (int q = 0; q < 4; q++) {
                    uint32_t bf[4];
                    ldmx4(bf, Bb + (b_off[q] ^ cb));
                    mma_fp8(c[0][q * 2 + 0], af[0], &bf[0]);
                    mma_fp8(c[0][q * 2 + 1], af[0], &bf[2]);
                    mma_fp8(c[1][q * 2 + 0], af[1], &bf[0]);
                    mma_fp8(c[1][q * 2 + 1], af[1], &bf[2]);
                }
            }
            st ^= 1;
        }

        // ---- epilogue (overlaps next tile's chunk-0 load) ----
        const bool diag = (rt == ct);
        const bool pos_tile = (ct == (rt ^ 32));

#pragma unroll
        for (int mf = 0; mf < 2; mf++)
#pragma unroll
            for (int nf = 0; nf < 8; nf++)
#pragma unroll
                for (int h = 0; h < 2; h++)
#pragma unroll
                    for (int e = 0; e < 2; e++) {
                        const int lr = lr0 + mf * 16 + h * 8;
                        const int lc = lc0 + nf * 8 + e;
                        const bool eq = (lr == lc);
                        const float sv = c[mf][nf][h * 2 + e];
                        if (pos_tile && eq) {
                            g_pos[row_base + lr] = sv;
                            g_pos[col_base + lc] = sv;
                        }
                        c[mf][nf][h * 2 + e] = (diag && eq) ? 0.0f : ex2f(sv * EXP_SCALE);
                    }

        // row sums (lanes sharing a row: bits 0-1)
#pragma unroll
        for (int mf = 0; mf < 2; mf++)
#pragma unroll
            for (int h = 0; h < 2; h++) {
                float v = 0.0f;
#pragma unroll
                for (int nf = 0; nf < 8; nf++)
                    v += c[mf][nf][h * 2 + 0] + c[mf][nf][h * 2 + 1];
                v += __shfl_xor_sync(0xffffffffu, v, 1);
                v += __shfl_xor_sync(0xffffffffu, v, 2);
                if ((lane & 3) == 0)
                    atomicAdd(&g_S[row_base + lr0 + mf * 16 + h * 8], v);
            }

        // col sums (transpose contribution; lanes sharing a col: bits 2-4)
        if (!diag) {
#pragma unroll
            for (int nf = 0; nf < 8; nf++)
#pragma unroll
                for (int e = 0; e < 2; e++) {
                    float v = c[0][nf][e] + c[0][nf][2 + e] + c[1][nf][e] + c[1][nf][2 + e];
                    v += __shfl_xor_sync(0xffffffffu, v, 4);
                    v += __shfl_xor_sync(0xffffffffu, v, 8);
                    v += __shfl_xor_sync(0xffffffffu, v, 16);
                    if (lane < 4)
                        atomicAdd(&g_S[col_base + lc0 + nf * 8 + e], v);
                }
        }

        cur = nxt; rt = nrt; ct = nct;
        row_base = rt * BT; col_base = ct * BT;
    }

    // ---- fused final loss: last CTA reduces g_S / g_pos ----
    __threadfence();
    __shared__ unsigned int s_last;
    __syncthreads();
    if (tid == 0) s_last = atomicAdd(&g_cnt, 1u);
    __syncthreads();
    if (s_last == NCTA - 1) {
        __threadfence();
        float acc = 0.0f;
        for (int i = tid; i < NROWS; i += THREADS)
            acc += -POS_SCALE * g_pos[i] + logf(g_S[i]);
#pragma unroll
        for (int m = 16; m; m >>= 1) acc += __shfl_xor_sync(0xffffffffu, acc, m);
        __shared__ float red[8];
        if (lane == 0) red[wid] = acc;
        __syncthreads();
        if (tid == 0) {
            float v = 0.0f;
#pragma unroll
            for (int w = 0; w < 8; w++) v += red[w];
            out[0] = v * (1.0f / NROWS);
            g_cnt = 0;   // reset for next graph replay (g_tile reset by norm)
        }
    }
}

extern "C" void kernel_launch(void* const* d_in, const int* in_sizes, int n_in,
                              void* d_out, int out_size) {
    const float* a = (const float*)d_in[0];
    const float* b = (const float*)d_in[1];
    (void)in_sizes; (void)n_in; (void)out_size;

    cudaFuncSetAttribute(gemm_kernel, cudaFuncAttributeMaxDynamicSharedMemorySize, SMEM_TOTAL);

    norm_kernel<<<NROWS / 8, 256>>>(a, b);
    gemm_kernel<<<NCTA, THREADS, SMEM_TOTAL>>>((float*)d_out);
}